// round 5
// baseline (speedup 1.0000x reference)
#include <cuda_runtime.h>

// GCN_33560874451187 — scalarized 2-layer GCN via counting-sort CSR.
// N=500000 nodes, E=16000000 int32 edges.
// Build CSR (rows grouped by target col) once; both aggregation passes are
// then atomic-free warp-per-node gather+reduce with fused epilogues.

#define NN      500000
#define NE      16000000
#define SCAN_B  1024                      // deg elements per scan block
#define NSB     ((NN + SCAN_B - 1) / SCAN_B)   // 489

__device__ int      g_deg[NN];
__device__ unsigned g_off[NN + 1];
__device__ unsigned g_cur[NN];
__device__ int      g_csr[NE];            // 64MB: source rows grouped by col
__device__ float    g_dinv[NN];
__device__ float    g_val[NN];            // layer-1 y = dinv*x
__device__ float    g_val2[NN];           // layer-2 z
__device__ unsigned g_bsum[NSB];
__device__ unsigned g_bscan[NSB];

// ---------------------------------------------------------------------------

__global__ void k_zero(int n) {
    int i = blockIdx.x * blockDim.x + threadIdx.x;
    if (i < n) g_deg[i] = 0;
}

// In-degree: col half only, int4 vectorized.
__global__ void k_deg(const int* __restrict__ col, int e4) {
    int i = blockIdx.x * blockDim.x + threadIdx.x;
    if (i < e4) {
        int4 c = ((const int4*)col)[i];
        atomicAdd(&g_deg[c.x], 1);
        atomicAdd(&g_deg[c.y], 1);
        atomicAdd(&g_deg[c.z], 1);
        atomicAdd(&g_deg[c.w], 1);
    }
}

// --- 3-stage exclusive scan of g_deg -> g_off ------------------------------

__global__ void k_bsum(int n) {
    __shared__ unsigned s_w[8];
    int b = blockIdx.x, t = threadIdx.x;
    unsigned s = 0;
    int base = b * SCAN_B + t * 4;
    #pragma unroll
    for (int j = 0; j < 4; j++) {
        int i = base + j;
        if (i < n) s += (unsigned)g_deg[i];
    }
    #pragma unroll
    for (int o = 16; o; o >>= 1) s += __shfl_xor_sync(~0u, s, o);
    if ((t & 31) == 0) s_w[t >> 5] = s;
    __syncthreads();
    if (t == 0) {
        unsigned tot = 0;
        #pragma unroll
        for (int w = 0; w < 8; w++) tot += s_w[w];
        g_bsum[b] = tot;
    }
}

__global__ void k_bscan(int nsb) {
    __shared__ unsigned s[512];
    int t = threadIdx.x;
    unsigned v = (t < nsb) ? g_bsum[t] : 0u;
    s[t] = v;
    __syncthreads();
    for (int st = 1; st < 512; st <<= 1) {
        unsigned u = (t >= st) ? s[t - st] : 0u;
        __syncthreads();
        s[t] += u;
        __syncthreads();
    }
    if (t < nsb) g_bscan[t] = s[t] - v;   // exclusive
}

// Final scan stage; also fuses phase1 (dinv, val) since deg is in hand.
__global__ void k_off(const float* __restrict__ x, int n, int e) {
    __shared__ unsigned s[256];
    int b = blockIdx.x, t = threadIdx.x;
    int base = b * SCAN_B + t * 4;
    unsigned d[4];
    unsigned lsum = 0;
    #pragma unroll
    for (int j = 0; j < 4; j++) {
        int i = base + j;
        d[j] = (i < n) ? (unsigned)g_deg[i] : 0u;
        lsum += d[j];
    }
    s[t] = lsum;
    __syncthreads();
    for (int st = 1; st < 256; st <<= 1) {
        unsigned u = (t >= st) ? s[t - st] : 0u;
        __syncthreads();
        s[t] += u;
        __syncthreads();
    }
    unsigned run = g_bscan[b] + s[t] - lsum;   // exclusive thread base
    #pragma unroll
    for (int j = 0; j < 4; j++) {
        int i = base + j;
        if (i < n) {
            g_off[i] = run;
            g_cur[i] = run;
            float dinv = rsqrtf((float)(d[j] + 1u));
            g_dinv[i] = dinv;
            g_val[i]  = dinv * x[i];
            run += d[j];
        }
    }
    if (b == 0 && t == 0) g_off[n] = (unsigned)e;
}

// Scatter rows into CSR segments (atomic cursor per target node).
__global__ void k_scatter(const int* __restrict__ row,
                          const int* __restrict__ col, int e4) {
    int i = blockIdx.x * blockDim.x + threadIdx.x;
    if (i < e4) {
        int4 r = ((const int4*)row)[i];
        int4 c = ((const int4*)col)[i];
        g_csr[atomicAdd(&g_cur[c.x], 1u)] = r.x;
        g_csr[atomicAdd(&g_cur[c.y], 1u)] = r.y;
        g_csr[atomicAdd(&g_cur[c.z], 1u)] = r.z;
        g_csr[atomicAdd(&g_cur[c.w], 1u)] = r.w;
    }
}

// --- atomic-free aggregation: one warp per node ----------------------------

// Layer 1: sum val over in-edges + self loop, then scalar MLP -> val2.
__global__ void k_agg1(const float* __restrict__ W1,
                       const float* __restrict__ b1,
                       const float* __restrict__ W2, int n) {
    int w = (blockIdx.x * blockDim.x + threadIdx.x) >> 5;
    int lane = threadIdx.x & 31;
    if (w >= n) return;
    unsigned o0 = g_off[w], o1 = g_off[w + 1];
    float sum = 0.0f;
    for (unsigned k = o0 + lane; k < o1; k += 32)
        sum += __ldg(&g_val[__ldg(&g_csr[k])]);
    #pragma unroll
    for (int s = 16; s; s >>= 1) sum += __shfl_xor_sync(~0u, sum, s);
    if (lane == 0) {
        float dinv = g_dinv[w];
        float s1 = dinv * (sum + g_val[w]);
        float t = 0.0f;
        #pragma unroll
        for (int k = 0; k < 10; k++) {
            float h = fmaf(s1, __ldg(&W1[k]), __ldg(&b1[k]));
            t = fmaf(fmaxf(h, 0.0f), __ldg(&W2[k]), t);
        }
        g_val2[w] = dinv * t;
    }
}

// Layer 2: sum val2 + self loop, bias, clip -> out.
__global__ void k_agg2(float* __restrict__ out,
                       const float* __restrict__ b2, int n) {
    int w = (blockIdx.x * blockDim.x + threadIdx.x) >> 5;
    int lane = threadIdx.x & 31;
    if (w >= n) return;
    unsigned o0 = g_off[w], o1 = g_off[w + 1];
    float sum = 0.0f;
    for (unsigned k = o0 + lane; k < o1; k += 32)
        sum += __ldg(&g_val2[__ldg(&g_csr[k])]);
    #pragma unroll
    for (int s = 16; s; s >>= 1) sum += __shfl_xor_sync(~0u, sum, s);
    if (lane == 0) {
        float v = fmaf(g_dinv[w], sum + g_val2[w], __ldg(&b2[0]));
        out[w] = fminf(fmaxf(v, -0.5f), 9.5f);
    }
}

// ---------------------------------------------------------------------------

extern "C" void kernel_launch(void* const* d_in, const int* in_sizes, int n_in,
                              void* d_out, int out_size) {
    const float* x   = (const float*)d_in[0];
    const int*   ei  = (const int*)d_in[1];
    const float* W1  = (const float*)d_in[2];
    const float* b1  = (const float*)d_in[3];
    const float* W2  = (const float*)d_in[4];
    const float* b2  = (const float*)d_in[5];
    float*       out = (float*)d_out;

    int n = in_sizes[0];
    int e = in_sizes[1] / 2;
    if (n > NN) n = NN;
    if (e > NE) e = NE;
    int e4 = e / 4;

    const int* row = ei;
    const int* col = ei + e;

    const int T = 256;
    int nb_n  = (n + T - 1) / T;
    int nb_e4 = (e4 + T - 1) / T;
    int nsb   = (n + SCAN_B - 1) / SCAN_B;
    int nb_w  = (n * 32 + T - 1) / T;      // warp-per-node grids

    k_zero<<<nb_n, T>>>(n);
    k_deg<<<nb_e4, T>>>(col, e4);
    k_bsum<<<nsb, 256>>>(n);
    k_bscan<<<1, 512>>>(nsb);
    k_off<<<nsb, 256>>>(x, n, e);
    k_scatter<<<nb_e4, T>>>(row, col, e4);
    k_agg1<<<nb_w, T>>>(W1, b1, W2, n);
    k_agg2<<<nb_w, T>>>(out, b2, n);
}

// round 8
// speedup vs baseline: 1.2302x; 1.2302x over previous
#include <cuda_runtime.h>

// GCN_33560874451187 — scalarized 2-layer GCN, tile-sorted two-level binning.
// N=500000, E=16000000 (int32 edges).
// Buckets: cb=col>>13 (62 ranges of 8192), rb=row>>14 (31 ranges of 16384).
// b = cb*32+rb. record = rowlocal(14)<<13 | collocal(13).
// k_bin sorts each 16K-edge tile in smem and emits contiguous bucket runs.
// deg/agg accumulate in smem over the 8192-col range; agg stages 64KB val
// slices per row range so ALL per-edge random traffic lives in smem.

#define NN     500000
#define NE     16000000
#define CBB    13
#define CBS    8192
#define NCB    62
#define RBB    14
#define RBS    16384
#define NB     1984          // 62*32 bucket id space
#define STRIDE 10240         // per-bucket capacity (mean 8324, +20 sigma)
#define TILE   16384
#define BTHR   512

__device__ unsigned g_bins[(size_t)NB * STRIDE];   // ~81MB
__device__ unsigned g_tail[NB];
__device__ int      g_deg[NN];
__device__ float    g_dinv[NN];
__device__ float    g_val[NN];
__device__ float    g_acc[NN];

// ---------------------------------------------------------------------------

__global__ void k_init(int n) {
    int i = blockIdx.x * blockDim.x + threadIdx.x;
    if (i < NB) g_tail[i] = 0u;
    if (i < n) g_deg[i] = 0;
}

// Tile-sorted binning. dyn smem:
//   s_sorted u32[16384] | s_cnt u32[1984] | s_lb u32[1984] | s_gb u32[1984]
//   | s_scan u32[512] | s_rank u16[16384]   = 124160 B
__global__ void k_bin(const int* __restrict__ row, const int* __restrict__ col, int e) {
    extern __shared__ unsigned sm[];
    unsigned* s_sorted = sm;                    // 16384
    unsigned* s_cnt    = sm + TILE;             // 1984
    unsigned* s_lb     = s_cnt + NB;            // 1984
    unsigned* s_gb     = s_lb + NB;             // 1984
    unsigned* s_scan   = s_gb + NB;             // 512
    unsigned short* s_rank = (unsigned short*)(s_scan + BTHR);  // 16384 u16

    int t = threadIdx.x;
    int tb = blockIdx.x * TILE;
    int nE = e - tb; if (nE > TILE) nE = TILE;

    for (int i = t; i < NB; i += BTHR) s_cnt[i] = 0u;
    __syncthreads();

    // rank within (tile, bucket)
    for (int k = t; k < nE; k += BTHR) {
        int r = row[tb + k], c = col[tb + k];
        unsigned b = ((unsigned)(c >> CBB) << 5) | (unsigned)(r >> RBB);
        s_rank[k] = (unsigned short)atomicAdd(&s_cnt[b], 1u);
    }
    __syncthreads();

    // exclusive scan of counts (thread owns 4 buckets) + global reservation
    unsigned c4[4], lsum = 0;
    int bb = t * 4;
    #pragma unroll
    for (int j = 0; j < 4; j++) {
        unsigned v = (bb + j < NB) ? s_cnt[bb + j] : 0u;
        c4[j] = v; lsum += v;
    }
    s_scan[t] = lsum;
    __syncthreads();
    for (int st = 1; st < BTHR; st <<= 1) {
        unsigned u = (t >= st) ? s_scan[t - st] : 0u;
        __syncthreads();
        s_scan[t] += u;
        __syncthreads();
    }
    unsigned run = s_scan[t] - lsum;
    #pragma unroll
    for (int j = 0; j < 4; j++) {
        if (bb + j < NB) {
            s_lb[bb + j] = run;
            if (c4[j]) s_gb[bb + j] = atomicAdd(&g_tail[bb + j], c4[j]);
            run += c4[j];
        }
    }
    __syncthreads();

    // smem shuffle into bucket-sorted order
    for (int k = t; k < nE; k += BTHR) {
        int r = row[tb + k], c = col[tb + k];           // L1/L2 hit
        unsigned b = ((unsigned)(c >> CBB) << 5) | (unsigned)(r >> RBB);
        unsigned rec = ((unsigned)(r & (RBS - 1)) << CBB) | (unsigned)(c & (CBS - 1));
        s_sorted[s_lb[b] + (unsigned)s_rank[k]] = rec;
    }
    __syncthreads();

    // contiguous copy-out: warp per bucket
    int w = t >> 5, lane = t & 31;
    for (int b = w; b < NB; b += (BTHR / 32)) {
        unsigned cnt = s_cnt[b];
        if (!cnt) continue;
        unsigned* dst = g_bins + (size_t)b * STRIDE + s_gb[b];
        unsigned lb = s_lb[b];
        for (unsigned i = lane; i < cnt; i += 32) dst[i] = s_sorted[lb + i];
    }
}

// In-degree: block = (cb, group of 4 rbs); 32KB smem counters.
__global__ void k_degb(int n) {
    __shared__ unsigned s_cnt[CBS];
    int t = threadIdx.x;
    int cb = blockIdx.x >> 3, g = blockIdx.x & 7;

    for (int i = t; i < CBS; i += BTHR) s_cnt[i] = 0u;
    __syncthreads();

    #pragma unroll
    for (int j = 0; j < 4; j++) {
        unsigned b = (unsigned)cb * 32u + (unsigned)(g * 4 + j);
        unsigned cnt = g_tail[b];
        const unsigned* recs = g_bins + (size_t)b * STRIDE;
        for (unsigned k = t; k < cnt; k += BTHR)
            atomicAdd(&s_cnt[recs[k] & (CBS - 1)], 1u);
    }
    __syncthreads();

    int base = cb << CBB;
    for (int i = t; i < CBS; i += BTHR) {
        unsigned c = s_cnt[i];
        if (c && base + i < n) atomicAdd(&g_deg[base + i], (int)c);
    }
}

// Aggregation: 32KB smem acc over col range + 64KB staged val slice per rb.
__global__ void k_aggb(int n) {
    extern __shared__ float smf[];
    float* s_acc = smf;          // 8192
    float* s_val = smf + CBS;    // 16384
    int t = threadIdx.x;
    int cb = blockIdx.x >> 3, g = blockIdx.x & 7;

    for (int i = t; i < CBS; i += BTHR) s_acc[i] = 0.0f;

    #pragma unroll
    for (int j = 0; j < 4; j++) {
        int rb = g * 4 + j;
        unsigned b = (unsigned)cb * 32u + (unsigned)rb;
        unsigned cnt = g_tail[b];
        const unsigned* recs = g_bins + (size_t)b * STRIDE;

        int rbase = rb << RBB;
        int rlim = n - rbase; if (rlim > RBS) rlim = RBS;
        __syncthreads();
        if (rlim > 0)
            for (int i = t; i < rlim; i += BTHR) s_val[i] = g_val[rbase + i];
        __syncthreads();

        for (unsigned k = t; k < cnt; k += BTHR) {
            unsigned rec = recs[k];
            atomicAdd(&s_acc[rec & (CBS - 1)], s_val[rec >> CBB]);
        }
    }
    __syncthreads();

    int base = cb << CBB;
    for (int i = t; i < CBS; i += BTHR) {
        float v = s_acc[i];
        if (v != 0.0f && base + i < n) atomicAdd(&g_acc[base + i], v);
    }
}

// --- node-wise kernels -----------------------------------------------------

__global__ void k_phase1(const float* __restrict__ x, int n) {
    int i = blockIdx.x * blockDim.x + threadIdx.x;
    if (i < n) {
        float dinv = rsqrtf((float)(g_deg[i] + 1));
        g_dinv[i] = dinv;
        float y = dinv * x[i];
        g_val[i] = y;
        g_acc[i] = y;
    }
}

__global__ void k_phase2(const float* __restrict__ W1,
                         const float* __restrict__ b1,
                         const float* __restrict__ W2, int n) {
    int i = blockIdx.x * blockDim.x + threadIdx.x;
    if (i < n) {
        float dinv = g_dinv[i];
        float s1 = dinv * g_acc[i];
        float tacc = 0.0f;
        #pragma unroll
        for (int k = 0; k < 10; k++) {
            float h = fmaf(s1, __ldg(&W1[k]), __ldg(&b1[k]));
            tacc = fmaf(fmaxf(h, 0.0f), __ldg(&W2[k]), tacc);
        }
        float z = dinv * tacc;
        g_val[i] = z;
        g_acc[i] = z;
    }
}

__global__ void k_out(float* __restrict__ out, const float* __restrict__ b2, int n) {
    int i = blockIdx.x * blockDim.x + threadIdx.x;
    if (i < n) {
        float v = fmaf(g_dinv[i], g_acc[i], __ldg(&b2[0]));
        out[i] = fminf(fmaxf(v, -0.5f), 9.5f);
    }
}

// ---------------------------------------------------------------------------

extern "C" void kernel_launch(void* const* d_in, const int* in_sizes, int n_in,
                              void* d_out, int out_size) {
    const float* x   = (const float*)d_in[0];
    const int*   ei  = (const int*)d_in[1];
    const float* W1  = (const float*)d_in[2];
    const float* b1  = (const float*)d_in[3];
    const float* W2  = (const float*)d_in[4];
    const float* b2  = (const float*)d_in[5];
    float*       out = (float*)d_out;

    int n = in_sizes[0];
    int e = in_sizes[1] / 2;
    if (n > NN) n = NN;
    if (e > NE) e = NE;

    const int* row = ei;
    const int* col = ei + e;

    const int BIN_SMEM = (TILE + 3 * NB + BTHR) * 4 + TILE * 2;  // 124160
    const int AGG_SMEM = (CBS + RBS) * 4;                        // 98304
    cudaFuncSetAttribute(k_bin,  cudaFuncAttributeMaxDynamicSharedMemorySize, BIN_SMEM);
    cudaFuncSetAttribute(k_aggb, cudaFuncAttributeMaxDynamicSharedMemorySize, AGG_SMEM);

    const int T = 256;
    int nb_n   = (n + T - 1) / T;
    int nb_bin = (e + TILE - 1) / TILE;    // 977
    int nb_agg = NCB * 8;                  // 496

    k_init<<<nb_n, T>>>(n);
    k_bin<<<nb_bin, BTHR, BIN_SMEM>>>(row, col, e);
    k_degb<<<nb_agg, BTHR>>>(n);
    k_phase1<<<nb_n, T>>>(x, n);
    k_aggb<<<nb_agg, BTHR, AGG_SMEM>>>(n);
    k_phase2<<<nb_n, T>>>(W1, b1, W2, n);
    k_aggb<<<nb_agg, BTHR, AGG_SMEM>>>(n);
    k_out<<<nb_n, T>>>(out, b2, n);
}

// round 10
// speedup vs baseline: 1.9080x; 1.5510x over previous
#include <cuda_runtime.h>

// GCN_33560874451187 — scalarized 2-layer GCN, single-level col binning.
// N=500000, E=16000000 (int32 edges).
// Bucket = col>>12 (123 buckets, 4096-col window). rec = collocal<<19 | row.
// k_bin tile-sorts 8192-edge tiles in smem, emits contiguous bucket runs.
// deg + both aggs consume bins with a 16KB smem window accumulator
// (random per-edge RMW moves from LTS to smem; gather stays at L2).

#define NN     500000
#define NE     16000000
#define CLB    12
#define CW     4096                 // col window size
#define NBK    123                  // ceil(NN/CW)
#define STRIDE 140000               // per-bucket capacity (mean ~131K, +24sd)
#define TILE   8192
#define BT     256
#define BPB    8                    // consumer blocks per bucket

__device__ unsigned g_bins[(size_t)NBK * STRIDE];  // ~69MB (L2-resident)
__device__ unsigned g_tail[NBK];
__device__ int      g_deg[NN];
__device__ float    g_dinv[NN];
__device__ float    g_val[NN];
__device__ float    g_acc[NN];

// ---------------------------------------------------------------------------

__global__ void k_zero_deg(int n) {
    int i = blockIdx.x * blockDim.x + threadIdx.x;
    if (i < n) g_deg[i] = 0;
}
__global__ void k_zero_tail() {
    int i = blockIdx.x * blockDim.x + threadIdx.x;
    if (i < NBK) g_tail[i] = 0u;
}

// Tile-sorted binning: rank -> 128-entry scan -> smem shuffle -> coalesced out.
__global__ void k_bin(const int* __restrict__ row, const int* __restrict__ col, int e) {
    __shared__ unsigned       s_sorted[TILE];   // 32KB
    __shared__ unsigned short s_rank[TILE];     // 16KB
    __shared__ unsigned s_cnt[128], s_lb[128], s_gb[128];

    int t = threadIdx.x;
    int tb = blockIdx.x * TILE;
    int nE = e - tb; if (nE > TILE) nE = TILE;

    if (t < 128) s_cnt[t] = 0u;
    __syncthreads();

    for (int k = t; k < nE; k += BT) {
        unsigned b = (unsigned)col[tb + k] >> CLB;
        s_rank[k] = (unsigned short)atomicAdd(&s_cnt[b], 1u);
    }
    __syncthreads();

    // exclusive scan of 128 counters: warp shfl-scan + warp-total fixup
    if (t < 128) {
        unsigned lane = t & 31, w = t >> 5;
        unsigned v = s_cnt[t], p = v;
        #pragma unroll
        for (int o = 1; o < 32; o <<= 1) {
            unsigned u = __shfl_up_sync(0xFFFFFFFFu, p, o);
            if (lane >= o) p += u;
        }
        s_lb[t] = p - v;                        // exclusive within warp
        if (lane == 31) s_gb[w] = p;            // warp total (temp)
    }
    __syncthreads();
    if (t < 128) {
        unsigned w = t >> 5, off = 0;
        for (unsigned j = 0; j < w; j++) off += s_gb[j];
        s_lb[t] += off;
    }
    __syncthreads();
    if (t < 128) {
        unsigned c = s_cnt[t];
        s_gb[t] = c ? atomicAdd(&g_tail[t], c) : 0u;
    }
    __syncthreads();

    for (int k = t; k < nE; k += BT) {
        int r = row[tb + k];                    // cold read
        int c = col[tb + k];                    // cache hit
        unsigned b = (unsigned)c >> CLB;
        unsigned rec = ((unsigned)(c & (CW - 1)) << 19) | (unsigned)r;
        s_sorted[s_lb[b] + (unsigned)s_rank[k]] = rec;
    }
    __syncthreads();

    // copy-out: warp per bucket (runs avg ~67 recs = ~268B, coalesced)
    int w = t >> 5, lane = t & 31;
    for (int b = w; b < NBK; b += (BT / 32)) {
        unsigned cnt = s_cnt[b];
        if (!cnt) continue;
        unsigned gb = s_gb[b];
        if (gb + cnt > STRIDE) cnt = (gb < STRIDE) ? (STRIDE - gb) : 0u;  // safety, never triggers
        unsigned* dst = g_bins + (size_t)b * STRIDE + gb;
        unsigned lb = s_lb[b];
        for (unsigned i = lane; i < cnt; i += 32) dst[i] = s_sorted[lb + i];
    }
}

// In-degree from bins: 16KB smem histogram per col window, 4M merge REDs.
__global__ void k_degb(int n) {
    __shared__ unsigned s_cnt[CW];
    int t = threadIdx.x;
    int b = blockIdx.x / BPB, j = blockIdx.x % BPB;
    unsigned cnt = g_tail[b]; if (cnt > STRIDE) cnt = STRIDE;
    unsigned start = (unsigned)(((unsigned long long)cnt * j) / BPB);
    unsigned end   = (unsigned)(((unsigned long long)cnt * (j + 1)) / BPB);

    for (int i = t; i < CW; i += BT) s_cnt[i] = 0u;
    __syncthreads();

    const unsigned* recs = g_bins + (size_t)b * STRIDE;
    for (unsigned k = start + t; k < end; k += BT)
        atomicAdd(&s_cnt[recs[k] >> 19], 1u);
    __syncthreads();

    int base = b << CLB;
    for (int i = t; i < CW; i += BT) {
        unsigned c = s_cnt[i];
        if (c && base + i < n) atomicAdd(&g_deg[base + i], (int)c);
    }
}

// Aggregation from bins: gather val (L2) + smem window accumulate + merge.
__global__ void k_aggb(int n) {
    __shared__ float s_acc[CW];
    int t = threadIdx.x;
    int b = blockIdx.x / BPB, j = blockIdx.x % BPB;
    unsigned cnt = g_tail[b]; if (cnt > STRIDE) cnt = STRIDE;
    unsigned start = (unsigned)(((unsigned long long)cnt * j) / BPB);
    unsigned end   = (unsigned)(((unsigned long long)cnt * (j + 1)) / BPB);

    for (int i = t; i < CW; i += BT) s_acc[i] = 0.0f;
    __syncthreads();

    const unsigned* recs = g_bins + (size_t)b * STRIDE;
    for (unsigned k = start + t; k < end; k += BT) {
        unsigned rec = recs[k];
        atomicAdd(&s_acc[rec >> 19], __ldg(&g_val[rec & 0x7FFFFu]));
    }
    __syncthreads();

    int base = b << CLB;
    for (int i = t; i < CW; i += BT) {
        float v = s_acc[i];
        if (v != 0.0f && base + i < n) atomicAdd(&g_acc[base + i], v);
    }
}

// --- node-wise kernels -----------------------------------------------------

__global__ void k_phase1(const float* __restrict__ x, int n) {
    int i = blockIdx.x * blockDim.x + threadIdx.x;
    if (i < n) {
        float dinv = rsqrtf((float)(g_deg[i] + 1));
        g_dinv[i] = dinv;
        float y = dinv * x[i];
        g_val[i] = y;
        g_acc[i] = y;
    }
}

__global__ void k_phase2(const float* __restrict__ W1,
                         const float* __restrict__ b1,
                         const float* __restrict__ W2, int n) {
    int i = blockIdx.x * blockDim.x + threadIdx.x;
    if (i < n) {
        float dinv = g_dinv[i];
        float s1 = dinv * g_acc[i];
        float tacc = 0.0f;
        #pragma unroll
        for (int k = 0; k < 10; k++) {
            float h = fmaf(s1, __ldg(&W1[k]), __ldg(&b1[k]));
            tacc = fmaf(fmaxf(h, 0.0f), __ldg(&W2[k]), tacc);
        }
        float z = dinv * tacc;
        g_val[i] = z;
        g_acc[i] = z;
    }
}

__global__ void k_out(float* __restrict__ out, const float* __restrict__ b2, int n) {
    int i = blockIdx.x * blockDim.x + threadIdx.x;
    if (i < n) {
        float v = fmaf(g_dinv[i], g_acc[i], __ldg(&b2[0]));
        out[i] = fminf(fmaxf(v, -0.5f), 9.5f);
    }
}

// ---------------------------------------------------------------------------

extern "C" void kernel_launch(void* const* d_in, const int* in_sizes, int n_in,
                              void* d_out, int out_size) {
    const float* x   = (const float*)d_in[0];
    const int*   ei  = (const int*)d_in[1];
    const float* W1  = (const float*)d_in[2];
    const float* b1  = (const float*)d_in[3];
    const float* W2  = (const float*)d_in[4];
    const float* b2  = (const float*)d_in[5];
    float*       out = (float*)d_out;

    int n = in_sizes[0];
    int e = in_sizes[1] / 2;
    if (n > NN) n = NN;
    if (e > NE) e = NE;

    const int* row = ei;
    const int* col = ei + e;

    const int T = 256;
    int nb_n   = (n + T - 1) / T;
    int nb_bin = (e + TILE - 1) / TILE;   // 1954
    int nb_con = NBK * BPB;               // 984

    // launch index 5 = first k_aggb (ncu captures -s 5 -c 1)
    k_zero_deg<<<nb_n, T>>>(n);                    // 0
    k_zero_tail<<<1, 128>>>();                     // 1
    k_bin<<<nb_bin, BT>>>(row, col, e);            // 2
    k_degb<<<nb_con, BT>>>(n);                     // 3
    k_phase1<<<nb_n, T>>>(x, n);                   // 4
    k_aggb<<<nb_con, BT>>>(n);                     // 5  <- profiled
    k_phase2<<<nb_n, T>>>(W1, b1, W2, n);          // 6
    k_aggb<<<nb_con, BT>>>(n);                     // 7
    k_out<<<nb_n, T>>>(out, b2, n);                // 8
}